// round 13
// baseline (speedup 1.0000x reference)
#include <cuda_runtime.h>
#include <cuda_fp16.h>
#include <cuda_bf16.h>
#include <cstdint>

#define NB 4
#define CC 24
#define EE 16
#define PP (768*768)
#define B1 288
#define PXB (PP/B1)        /* 2048 pixels per block */
#define TILES (PXB/256)    /* 8 tiles of 256 px */
#define AROW 264           /* one-hot row stride in shorts (528 B) */
#define XROW 24            /* x-tile row stride in shorts (48 B) */
#define VT_BLOCKS ((B1 + 25) * NB)   /* total blocks of k_var_trip */

__device__ float g_sums[NB*CC*EE];
__device__ float g_cnt[NB*CC];
__device__ float g_var[NB*CC];
__device__ float g_tsum[NB];
__device__ float g_tcnt[NB];
__device__ unsigned g_ticket;

// pack two f32 into f16x2: low half = a, high half = b
__device__ __forceinline__ unsigned pack_f16x2(float a, float b) {
    unsigned r;
    asm("cvt.rn.f16x2.f32 %0, %1, %2;" : "=r"(r) : "f"(b), "f"(a));
    return r;
}

// ---------------------------------------------------------------------------
// K1: segment sums via tensor cores.
// Per 256-px tile: D[32seg][16ch] += onehot^T(32x256) @ X(256x16), f16 MMA,
// f32 register accumulators across all tiles. Counts via match+popc leaders.
// State contract: all g_* accumulators are ZERO on kernel entry (module-load
// init on first call; re-zeroed by the k_var_trip tail on every call).
// ---------------------------------------------------------------------------
__global__ __launch_bounds__(256) void k_sums(const float* __restrict__ x,
                                              const int* __restrict__ tgt) {
    const int n = blockIdx.y;
    __shared__ __align__(16) unsigned short Atile[32*AROW];   // one-hot [seg][px]
    __shared__ __align__(16) unsigned short Xtile[256*XROW];  // f16 [px][ch]
    __shared__ float bins[32][16];
    __shared__ int   cnts[8][CC];
    const int tid  = threadIdx.x;
    const int wid  = tid >> 5;
    const int lane = tid & 31;

    for (int i = tid; i < 32*AROW; i += 256) Atile[i] = 0;
    for (int i = tid; i < 512;     i += 256) (&bins[0][0])[i] = 0.f;
    for (int i = tid; i < 8*CC;    i += 256) (&cnts[0][0])[i] = 0;
    __syncthreads();

    const float* xn = x   + (size_t)n * EE * PP;
    const int*   tn = tgt + (size_t)n * PP;
    const unsigned lmask = (1u << lane) - 1u;

    const int q  = wid >> 1;          // quadrant 0..3
    const int kh = wid & 1;           // K-half
    const int Mt = q >> 1, Nt = q & 1;
    const unsigned smemA = (unsigned)__cvta_generic_to_shared(Atile);
    const unsigned smemX = (unsigned)__cvta_generic_to_shared(Xtile);

    float d0 = 0.f, d1 = 0.f, d2 = 0.f, d3 = 0.f;
    int prev_seg = -1;
    const int pxbase = blockIdx.x * PXB;

    for (int t = 0; t < TILES; ++t) {
        const int p = pxbase + t*256 + tid;
        const int seg = tn[p];

        // counts (leader of each match-group, distinct segs -> race-free)
        const unsigned mm = __match_any_sync(0xffffffffu, seg);
        if ((mm & lmask) == 0u) cnts[wid][seg] += __popc(mm);

        // unscatter previous one-hot, scatter new (2-byte writes)
        if (prev_seg >= 0) Atile[prev_seg*AROW + tid] = 0;
        Atile[seg*AROW + tid] = 0x3C00;   // f16 1.0
        prev_seg = seg;

        // load 16 channels, convert to f16 pairs, store x-tile row
        float v[EE];
#pragma unroll
        for (int e = 0; e < EE; ++e) v[e] = xn[e*PP + p];
        unsigned pk[8];
#pragma unroll
        for (int j = 0; j < 8; ++j)
            pk[j] = pack_f16x2(v[2*j], v[2*j+1]);
        uint4* xr = reinterpret_cast<uint4*>(&Xtile[tid*XROW]);
        xr[0] = make_uint4(pk[0], pk[1], pk[2], pk[3]);
        xr[1] = make_uint4(pk[4], pk[5], pk[6], pk[7]);
        __syncthreads();

        // MMA phase: this warp's quadrant, its 8 K-steps
#pragma unroll
        for (int j = 0; j < 8; ++j) {
            const int Ks = kh*8 + j;
            unsigned a0, a1, a2, a3, b0, b1;
            const unsigned aaddr = smemA
                + (unsigned)(((Mt*16 + (lane & 15))*AROW + Ks*16)*2 + (lane >> 4)*16);
            asm volatile("ldmatrix.sync.aligned.m8n8.x4.shared.b16 "
                         "{%0,%1,%2,%3},[%4];"
                         : "=r"(a0), "=r"(a1), "=r"(a2), "=r"(a3) : "r"(aaddr));
            const unsigned baddr = smemX
                + (unsigned)(((Ks*16 + (lane & 15))*XROW)*2 + Nt*16);
            asm volatile("ldmatrix.sync.aligned.m8n8.x2.trans.shared.b16 "
                         "{%0,%1},[%2];"
                         : "=r"(b0), "=r"(b1) : "r"(baddr));
            asm volatile("mma.sync.aligned.m16n8k16.row.col.f32.f16.f16.f32 "
                         "{%0,%1,%2,%3},{%4,%5,%6,%7},{%8,%9},{%0,%1,%2,%3};"
                         : "+f"(d0), "+f"(d1), "+f"(d2), "+f"(d3)
                         : "r"(a0), "r"(a1), "r"(a2), "r"(a3), "r"(b0), "r"(b1));
        }
        __syncthreads();
    }

    // combine register fragments (two K-half warps per quadrant) via smem atomics
    {
        const int r0 = Mt*16 + (lane >> 2);
        const int c0 = Nt*8 + (lane & 3)*2;
        atomicAdd(&bins[r0][c0],     d0);
        atomicAdd(&bins[r0][c0+1],   d1);
        atomicAdd(&bins[r0+8][c0],   d2);
        atomicAdd(&bins[r0+8][c0+1], d3);
    }
    __syncthreads();

    for (int i = tid; i < CC*EE; i += 256)
        atomicAdd(&g_sums[n*CC*EE + i], bins[i >> 4][i & 15]);
    if (tid < CC) {
        int s = 0;
#pragma unroll
        for (int w = 0; w < 8; ++w) s += cnts[w][tid];
        atomicAdd(&g_cnt[n*CC + tid], (float)s);
    }
}

// ---------------------------------------------------------------------------
// K2 (fused): blockIdx.x < B1 -> variance slice; else -> triplet row-block.
// Variance: per-THREAD private smem bins -> zero warp machinery per pixel.
// Last finishing block computes the loss and re-zeros all state.
// ---------------------------------------------------------------------------
__device__ __forceinline__ void var_block(const float* __restrict__ x,
                                          const int* __restrict__ tgt,
                                          int n, int bx) {
    __shared__ __align__(16) float ms[CC][20];   // 5 quads/row, coprime with 8
    __shared__ float bins[256][25];              // thread-private rows, 25.6 KB
    __shared__ float vb[8][CC];
    const int tid  = threadIdx.x;
    const int wid  = tid >> 5;
    const int lane = tid & 31;

    for (int i = tid; i < CC*EE; i += 256)
        ms[i/EE][i%EE] = g_sums[n*CC*EE + i] / g_cnt[n*CC + i/EE];
#pragma unroll
    for (int i = 0; i < 25; ++i) bins[tid][i] = 0.f;
    __syncthreads();

    const float* xn = x   + (size_t)n * EE * PP;
    const int*   tn = tgt + (size_t)n * PP;

    int p = bx * PXB + tid;
#pragma unroll 2
    for (int it = 0; it < PXB/256; ++it, p += 256) {
        const int seg = tn[p];
        float xv[EE];
#pragma unroll
        for (int e = 0; e < EE; ++e) xv[e] = xn[e*PP + p];
        const float4* mq = reinterpret_cast<const float4*>(&ms[seg][0]);
        const float4 m0 = mq[0], m1 = mq[1], m2 = mq[2], m3 = mq[3];
        float d2 = 0.f, t;
        t = xv[0]-m0.x;  d2 += t*t;  t = xv[1]-m0.y;  d2 += t*t;
        t = xv[2]-m0.z;  d2 += t*t;  t = xv[3]-m0.w;  d2 += t*t;
        t = xv[4]-m1.x;  d2 += t*t;  t = xv[5]-m1.y;  d2 += t*t;
        t = xv[6]-m1.z;  d2 += t*t;  t = xv[7]-m1.w;  d2 += t*t;
        t = xv[8]-m2.x;  d2 += t*t;  t = xv[9]-m2.y;  d2 += t*t;
        t = xv[10]-m2.z; d2 += t*t;  t = xv[11]-m2.w; d2 += t*t;
        t = xv[12]-m3.x; d2 += t*t;  t = xv[13]-m3.y; d2 += t*t;
        t = xv[14]-m3.z; d2 += t*t;  t = xv[15]-m3.w; d2 += t*t;
        float h = fmaxf(sqrtf(d2) - 0.5f, 0.f);
        bins[tid][seg] += h * h;     // thread-private: race-free, no sync
    }
    __syncthreads();

    // column reduction: warp w, lane<24 sums rows [32w, 32w+32) of its seg
    if (lane < CC) {
        float acc = 0.f;
#pragma unroll
        for (int r = 0; r < 32; ++r) acc += bins[wid*32 + r][lane];
        vb[wid][lane] = acc;
    }
    __syncthreads();
    if (tid < CC) {
        float s = 0.f;
#pragma unroll
        for (int w = 0; w < 8; ++w) s += vb[w][tid];
        atomicAdd(&g_var[n*CC + tid], s);
    }
}

__device__ __forceinline__ void triplet_block(const int* __restrict__ ea,
                                              const int* __restrict__ er,
                                              int n, int rb) {
    __shared__ float cm[CC][EE];
    __shared__ float dr[200];
    __shared__ int r0s[200], r1s[200];
    __shared__ float da8[8];
    __shared__ int a0s[8], a1s[8];
    __shared__ float reds[256];
    __shared__ int   redc[256];
    const int tid = threadIdx.x;

    for (int i = tid; i < CC*EE; i += 256)
        cm[i/EE][i%EE] = g_sums[n*CC*EE + i] / g_cnt[n*CC + i/EE];
    __syncthreads();

    if (tid < 200) {
        int i0 = er[n*400 + tid], i1 = er[n*400 + 200 + tid];
        r0s[tid] = i0; r1s[tid] = i1;
        float s = 0.f;
#pragma unroll
        for (int e = 0; e < EE; ++e) {
            float df = cm[i0][e] - cm[i1][e] + 1e-6f;
            s += df * df;
        }
        dr[tid] = s;
    }
    if (tid < 8) {
        int a = rb*8 + tid;
        int i0 = ea[n*400 + a], i1 = ea[n*400 + 200 + a];
        a0s[tid] = i0; a1s[tid] = i1;
        float s = 0.f;
#pragma unroll
        for (int e = 0; e < EE; ++e) {
            float df = cm[i0][e] - cm[i1][e] + 1e-6f;
            s += df * df;
        }
        da8[tid] = s;
    }
    __syncthreads();

    float sum = 0.f; int cnt = 0;
    if (tid < 200) {
        const int rr0 = r0s[tid], rr1 = r1s[tid];
        const float drv = dr[tid];
#pragma unroll
        for (int a = 0; a < 8; ++a) {
            const int m = (a0s[a] == rr0) + (a0s[a] == rr1) +
                          (a1s[a] == rr0) + (a1s[a] == rr1);
            if (m == 1) {
                float t = 0.5f * (da8[a] - drv) + 0.01f;
                if (t > 0.f) { sum += t; cnt++; }
            }
        }
    }
    reds[tid] = sum; redc[tid] = cnt;
    __syncthreads();
    for (int s = 128; s > 0; s >>= 1) {
        if (tid < s) { reds[tid] += reds[tid + s]; redc[tid] += redc[tid + s]; }
        __syncthreads();
    }
    if (tid == 0) {
        atomicAdd(&g_tsum[n], reds[0]);
        atomicAdd(&g_tcnt[n], (float)redc[0]);
    }
}

__global__ __launch_bounds__(256) void k_var_trip(const float* __restrict__ x,
                                                  const int* __restrict__ tgt,
                                                  const int* __restrict__ ea,
                                                  const int* __restrict__ er,
                                                  float* __restrict__ out) {
    const int n = blockIdx.y;
    if (blockIdx.x < B1) var_block(x, tgt, n, blockIdx.x);
    else                 triplet_block(ea, er, n, blockIdx.x - B1);

    // ---- last-block finalize + state reset ----
    __threadfence();
    __shared__ unsigned isLast;
    const int tid = threadIdx.x;
    if (tid == 0)
        isLast = (atomicAdd(&g_ticket, 1u) == (unsigned)(VT_BLOCKS - 1));
    __syncthreads();
    if (!isLast) return;
    __threadfence();   // acquire: see all other blocks' atomics

    __shared__ float red[256];
    float acc = 0.f;
    if (tid < NB*CC) {
        float inv = 1.f / g_cnt[tid];
        float vt = g_var[tid] * inv;
        float s2 = 0.f;
#pragma unroll
        for (int e = 0; e < EE; ++e) {
            float m = g_sums[tid*EE + e] * inv;
            s2 += m * m;
        }
        float rg = sqrtf(s2) - 1.f;
        acc = (vt + rg * rg) * (1.f / (float)CC);
    }
    if (tid < NB) acc += (g_tcnt[tid] > 0.f) ? g_tsum[tid] / g_tcnt[tid] : 0.f;
    red[tid] = acc;
    __syncthreads();
    for (int s = 128; s > 0; s >>= 1) {
        if (tid < s) red[tid] += red[tid + s];
        __syncthreads();
    }
    if (tid == 0) out[0] = red[0] / 16.f;

    // re-zero all accumulator state for the next call (graph replay)
    for (int i = tid; i < NB*CC*EE; i += 256) g_sums[i] = 0.f;
    if (tid < NB*CC) { g_cnt[tid] = 0.f; g_var[tid] = 0.f; }
    if (tid < NB) { g_tsum[tid] = 0.f; g_tcnt[tid] = 0.f; }
    if (tid == 0) g_ticket = 0u;
}

// ---------------------------------------------------------------------------
extern "C" void kernel_launch(void* const* d_in, const int* in_sizes, int n_in,
                              void* d_out, int out_size) {
    const float* x   = (const float*)d_in[0];
    const int*   tgt = (const int*)d_in[1];
    const int*   ea  = (const int*)d_in[2];
    const int*   er  = (const int*)d_in[3];
    float* out = (float*)d_out;

    dim3 g(B1, NB);
    k_sums<<<g, 256>>>(x, tgt);
    dim3 gv(B1 + 25, NB);
    k_var_trip<<<gv, 256>>>(x, tgt, ea, er, out);
}

// round 14
// speedup vs baseline: 1.0246x; 1.0246x over previous
#include <cuda_runtime.h>
#include <cuda_fp16.h>
#include <cuda_bf16.h>
#include <cstdint>

#define NB 4
#define CC 24
#define EE 16
#define PP (768*768)
#define B1 288
#define PXB (PP/B1)        /* 2048 pixels per block */
#define TILES (PXB/256)    /* 8 tiles of 256 px */
#define AROW 264           /* one-hot row stride in shorts (528 B) */
#define XROW 24            /* x-tile row stride in shorts (48 B) */
#define VT_BLOCKS ((B1 + 25) * NB)   /* total blocks of k_var_trip */

__device__ float g_sums[NB*CC*EE];
__device__ float g_cnt[NB*CC];
__device__ float g_var[NB*CC];
__device__ float g_tsum[NB];
__device__ float g_tcnt[NB];
__device__ unsigned g_ticket;

// pack two f32 into f16x2: low half = a, high half = b
__device__ __forceinline__ unsigned pack_f16x2(float a, float b) {
    unsigned r;
    asm("cvt.rn.f16x2.f32 %0, %1, %2;" : "=r"(r) : "f"(b), "f"(a));
    return r;
}

// ---------------------------------------------------------------------------
// K1: segment sums via tensor cores (unchanged, passing at rel_err 0).
// ---------------------------------------------------------------------------
__global__ __launch_bounds__(256) void k_sums(const float* __restrict__ x,
                                              const int* __restrict__ tgt) {
    const int n = blockIdx.y;
    __shared__ __align__(16) unsigned short Atile[32*AROW];   // one-hot [seg][px]
    __shared__ __align__(16) unsigned short Xtile[256*XROW];  // f16 [px][ch]
    __shared__ float bins[32][16];
    __shared__ int   cnts[8][CC];
    const int tid  = threadIdx.x;
    const int wid  = tid >> 5;
    const int lane = tid & 31;

    for (int i = tid; i < 32*AROW; i += 256) Atile[i] = 0;
    for (int i = tid; i < 512;     i += 256) (&bins[0][0])[i] = 0.f;
    for (int i = tid; i < 8*CC;    i += 256) (&cnts[0][0])[i] = 0;
    __syncthreads();

    const float* xn = x   + (size_t)n * EE * PP;
    const int*   tn = tgt + (size_t)n * PP;
    const unsigned lmask = (1u << lane) - 1u;

    const int q  = wid >> 1;          // quadrant 0..3
    const int kh = wid & 1;           // K-half
    const int Mt = q >> 1, Nt = q & 1;
    const unsigned smemA = (unsigned)__cvta_generic_to_shared(Atile);
    const unsigned smemX = (unsigned)__cvta_generic_to_shared(Xtile);

    float d0 = 0.f, d1 = 0.f, d2 = 0.f, d3 = 0.f;
    int prev_seg = -1;
    const int pxbase = blockIdx.x * PXB;

    for (int t = 0; t < TILES; ++t) {
        const int p = pxbase + t*256 + tid;
        const int seg = tn[p];

        const unsigned mm = __match_any_sync(0xffffffffu, seg);
        if ((mm & lmask) == 0u) cnts[wid][seg] += __popc(mm);

        if (prev_seg >= 0) Atile[prev_seg*AROW + tid] = 0;
        Atile[seg*AROW + tid] = 0x3C00;   // f16 1.0
        prev_seg = seg;

        float v[EE];
#pragma unroll
        for (int e = 0; e < EE; ++e) v[e] = xn[e*PP + p];
        unsigned pk[8];
#pragma unroll
        for (int j = 0; j < 8; ++j)
            pk[j] = pack_f16x2(v[2*j], v[2*j+1]);
        uint4* xr = reinterpret_cast<uint4*>(&Xtile[tid*XROW]);
        xr[0] = make_uint4(pk[0], pk[1], pk[2], pk[3]);
        xr[1] = make_uint4(pk[4], pk[5], pk[6], pk[7]);
        __syncthreads();

#pragma unroll
        for (int j = 0; j < 8; ++j) {
            const int Ks = kh*8 + j;
            unsigned a0, a1, a2, a3, b0, b1;
            const unsigned aaddr = smemA
                + (unsigned)(((Mt*16 + (lane & 15))*AROW + Ks*16)*2 + (lane >> 4)*16);
            asm volatile("ldmatrix.sync.aligned.m8n8.x4.shared.b16 "
                         "{%0,%1,%2,%3},[%4];"
                         : "=r"(a0), "=r"(a1), "=r"(a2), "=r"(a3) : "r"(aaddr));
            const unsigned baddr = smemX
                + (unsigned)(((Ks*16 + (lane & 15))*XROW)*2 + Nt*16);
            asm volatile("ldmatrix.sync.aligned.m8n8.x2.trans.shared.b16 "
                         "{%0,%1},[%2];"
                         : "=r"(b0), "=r"(b1) : "r"(baddr));
            asm volatile("mma.sync.aligned.m16n8k16.row.col.f32.f16.f16.f32 "
                         "{%0,%1,%2,%3},{%4,%5,%6,%7},{%8,%9},{%0,%1,%2,%3};"
                         : "+f"(d0), "+f"(d1), "+f"(d2), "+f"(d3)
                         : "r"(a0), "r"(a1), "r"(a2), "r"(a3), "r"(b0), "r"(b1));
        }
        __syncthreads();
    }

    {
        const int r0 = Mt*16 + (lane >> 2);
        const int c0 = Nt*8 + (lane & 3)*2;
        atomicAdd(&bins[r0][c0],     d0);
        atomicAdd(&bins[r0][c0+1],   d1);
        atomicAdd(&bins[r0+8][c0],   d2);
        atomicAdd(&bins[r0+8][c0+1], d3);
    }
    __syncthreads();

    for (int i = tid; i < CC*EE; i += 256)
        atomicAdd(&g_sums[n*CC*EE + i], bins[i >> 4][i & 15]);
    if (tid < CC) {
        int s = 0;
#pragma unroll
        for (int w = 0; w < 8; ++w) s += cnts[w][tid];
        atomicAdd(&g_cnt[n*CC + tid], (float)s);
    }
}

// ---------------------------------------------------------------------------
// K2 (fused): var / triplet / last-block finalize, with UNIONED shared memory
// so the footprint is max() not sum() -> 8 blocks/SM.
// ---------------------------------------------------------------------------
struct VarS {
    float ms[CC][17];          // 17 coprime 32: conflict-free scalar reads
    float bins[256][25];       // thread-private rows (25 coprime 32)
    float vb[8][CC];
};
struct TripS {
    float cm[CC][EE];
    float dr[200];
    int   r0s[200], r1s[200];
    float da8[8];
    int   a0s[8], a1s[8];
    float reds[256];
    int   redc[256];
};
struct FinS { float red[256]; };
union ShU { VarS v; TripS t; FinS f; };

__device__ __forceinline__ void var_block(ShU& sh,
                                          const float* __restrict__ x,
                                          const int* __restrict__ tgt,
                                          int n, int bx) {
    VarS& S = sh.v;
    const int tid  = threadIdx.x;
    const int wid  = tid >> 5;
    const int lane = tid & 31;

    for (int i = tid; i < CC*EE; i += 256)
        S.ms[i/EE][i%EE] = g_sums[n*CC*EE + i] / g_cnt[n*CC + i/EE];
#pragma unroll
    for (int i = 0; i < 25; ++i) S.bins[tid][i] = 0.f;
    __syncthreads();

    const float* xn = x   + (size_t)n * EE * PP;
    const int*   tn = tgt + (size_t)n * PP;

    int p = bx * PXB + tid;
    for (int it = 0; it < PXB/256; ++it, p += 256) {
        const int seg = tn[p];
        float d2 = 0.f;
#pragma unroll
        for (int e = 0; e < EE; ++e) {
            float diff = xn[e*PP + p] - S.ms[seg][e];
            d2 += diff * diff;
        }
        float h = fmaxf(sqrtf(d2) - 0.5f, 0.f);
        S.bins[tid][seg] += h * h;    // thread-private: race-free, no sync
    }
    __syncthreads();

    if (lane < CC) {
        float acc = 0.f;
#pragma unroll
        for (int r = 0; r < 32; ++r) acc += S.bins[wid*32 + r][lane];
        S.vb[wid][lane] = acc;
    }
    __syncthreads();
    if (tid < CC) {
        float s = 0.f;
#pragma unroll
        for (int w = 0; w < 8; ++w) s += S.vb[w][tid];
        atomicAdd(&g_var[n*CC + tid], s);
    }
}

__device__ __forceinline__ void triplet_block(ShU& sh,
                                              const int* __restrict__ ea,
                                              const int* __restrict__ er,
                                              int n, int rb) {
    TripS& S = sh.t;
    const int tid = threadIdx.x;

    for (int i = tid; i < CC*EE; i += 256)
        S.cm[i/EE][i%EE] = g_sums[n*CC*EE + i] / g_cnt[n*CC + i/EE];
    __syncthreads();

    if (tid < 200) {
        int i0 = er[n*400 + tid], i1 = er[n*400 + 200 + tid];
        S.r0s[tid] = i0; S.r1s[tid] = i1;
        float s = 0.f;
#pragma unroll
        for (int e = 0; e < EE; ++e) {
            float df = S.cm[i0][e] - S.cm[i1][e] + 1e-6f;
            s += df * df;
        }
        S.dr[tid] = s;
    }
    if (tid < 8) {
        int a = rb*8 + tid;
        int i0 = ea[n*400 + a], i1 = ea[n*400 + 200 + a];
        S.a0s[tid] = i0; S.a1s[tid] = i1;
        float s = 0.f;
#pragma unroll
        for (int e = 0; e < EE; ++e) {
            float df = S.cm[i0][e] - S.cm[i1][e] + 1e-6f;
            s += df * df;
        }
        S.da8[tid] = s;
    }
    __syncthreads();

    float sum = 0.f; int cnt = 0;
    if (tid < 200) {
        const int rr0 = S.r0s[tid], rr1 = S.r1s[tid];
        const float drv = S.dr[tid];
#pragma unroll
        for (int a = 0; a < 8; ++a) {
            const int m = (S.a0s[a] == rr0) + (S.a0s[a] == rr1) +
                          (S.a1s[a] == rr0) + (S.a1s[a] == rr1);
            if (m == 1) {
                float t = 0.5f * (S.da8[a] - drv) + 0.01f;
                if (t > 0.f) { sum += t; cnt++; }
            }
        }
    }
    S.reds[tid] = sum; S.redc[tid] = cnt;
    __syncthreads();
    for (int s = 128; s > 0; s >>= 1) {
        if (tid < s) { S.reds[tid] += S.reds[tid + s]; S.redc[tid] += S.redc[tid + s]; }
        __syncthreads();
    }
    if (tid == 0) {
        atomicAdd(&g_tsum[n], S.reds[0]);
        atomicAdd(&g_tcnt[n], (float)S.redc[0]);
    }
}

__global__ __launch_bounds__(256, 8) void k_var_trip(const float* __restrict__ x,
                                                     const int* __restrict__ tgt,
                                                     const int* __restrict__ ea,
                                                     const int* __restrict__ er,
                                                     float* __restrict__ out) {
    __shared__ __align__(16) ShU sh;
    const int n = blockIdx.y;
    if (blockIdx.x < B1) var_block(sh, x, tgt, n, blockIdx.x);
    else                 triplet_block(sh, ea, er, n, blockIdx.x - B1);

    // ---- last-block finalize + state reset ----
    __threadfence();
    __shared__ unsigned isLast;
    const int tid = threadIdx.x;
    if (tid == 0)
        isLast = (atomicAdd(&g_ticket, 1u) == (unsigned)(VT_BLOCKS - 1));
    __syncthreads();
    if (!isLast) return;
    __threadfence();   // acquire: see all other blocks' atomics

    float acc = 0.f;
    if (tid < NB*CC) {
        float inv = 1.f / g_cnt[tid];
        float vt = g_var[tid] * inv;
        float s2 = 0.f;
#pragma unroll
        for (int e = 0; e < EE; ++e) {
            float m = g_sums[tid*EE + e] * inv;
            s2 += m * m;
        }
        float rg = sqrtf(s2) - 1.f;
        acc = (vt + rg * rg) * (1.f / (float)CC);
    }
    if (tid < NB) acc += (g_tcnt[tid] > 0.f) ? g_tsum[tid] / g_tcnt[tid] : 0.f;
    __syncthreads();          // all prior smem reads done before reuse
    sh.f.red[tid] = acc;
    __syncthreads();
    for (int s = 128; s > 0; s >>= 1) {
        if (tid < s) sh.f.red[tid] += sh.f.red[tid + s];
        __syncthreads();
    }
    if (tid == 0) out[0] = sh.f.red[0] / 16.f;

    // re-zero all accumulator state for the next call (graph replay)
    for (int i = tid; i < NB*CC*EE; i += 256) g_sums[i] = 0.f;
    if (tid < NB*CC) { g_cnt[tid] = 0.f; g_var[tid] = 0.f; }
    if (tid < NB) { g_tsum[tid] = 0.f; g_tcnt[tid] = 0.f; }
    if (tid == 0) g_ticket = 0u;
}

// ---------------------------------------------------------------------------
extern "C" void kernel_launch(void* const* d_in, const int* in_sizes, int n_in,
                              void* d_out, int out_size) {
    const float* x   = (const float*)d_in[0];
    const int*   tgt = (const int*)d_in[1];
    const int*   ea  = (const int*)d_in[2];
    const int*   er  = (const int*)d_in[3];
    float* out = (float*)d_out;

    dim3 g(B1, NB);
    k_sums<<<g, 256>>>(x, tgt);
    dim3 gv(B1 + 25, NB);
    k_var_trip<<<gv, 256>>>(x, tgt, ea, er, out);
}

// round 15
// speedup vs baseline: 1.1046x; 1.0780x over previous
#include <cuda_runtime.h>
#include <cuda_fp16.h>
#include <cuda_bf16.h>
#include <cstdint>

#define NB 4
#define CC 24
#define EE 16
#define PP (768*768)
#define B1 288
#define PXB (PP/B1)        /* 2048 pixels per block */
#define TILES (PXB/256)    /* 8 tiles of 256 px */
#define AROW 264           /* one-hot row stride in shorts (528 B) */
#define XROW 24            /* x-tile row stride in shorts (48 B) */
#define VT_BLOCKS ((B1 + 25) * NB)   /* total blocks of k_var_trip */

__device__ float g_sums[NB*CC*EE];
__device__ float g_cnt[NB*CC];
__device__ float g_var[NB*CC];
__device__ float g_tsum[NB];
__device__ float g_tcnt[NB];
__device__ unsigned g_ticket;

// pack two f32 into f16x2: low half = a, high half = b
__device__ __forceinline__ unsigned pack_f16x2(float a, float b) {
    unsigned r;
    asm("cvt.rn.f16x2.f32 %0, %1, %2;" : "=r"(r) : "f"(b), "f"(a));
    return r;
}

// ---------------------------------------------------------------------------
// K1: segment sums via tensor cores (unchanged, passing at rel_err 0).
// ---------------------------------------------------------------------------
__global__ __launch_bounds__(256) void k_sums(const float* __restrict__ x,
                                              const int* __restrict__ tgt) {
    const int n = blockIdx.y;
    __shared__ __align__(16) unsigned short Atile[32*AROW];   // one-hot [seg][px]
    __shared__ __align__(16) unsigned short Xtile[256*XROW];  // f16 [px][ch]
    __shared__ float bins[32][16];
    __shared__ int   cnts[8][CC];
    const int tid  = threadIdx.x;
    const int wid  = tid >> 5;
    const int lane = tid & 31;

    for (int i = tid; i < 32*AROW; i += 256) Atile[i] = 0;
    for (int i = tid; i < 512;     i += 256) (&bins[0][0])[i] = 0.f;
    for (int i = tid; i < 8*CC;    i += 256) (&cnts[0][0])[i] = 0;
    __syncthreads();

    const float* xn = x   + (size_t)n * EE * PP;
    const int*   tn = tgt + (size_t)n * PP;
    const unsigned lmask = (1u << lane) - 1u;

    const int q  = wid >> 1;          // quadrant 0..3
    const int kh = wid & 1;           // K-half
    const int Mt = q >> 1, Nt = q & 1;
    const unsigned smemA = (unsigned)__cvta_generic_to_shared(Atile);
    const unsigned smemX = (unsigned)__cvta_generic_to_shared(Xtile);

    float d0 = 0.f, d1 = 0.f, d2 = 0.f, d3 = 0.f;
    int prev_seg = -1;
    const int pxbase = blockIdx.x * PXB;

    for (int t = 0; t < TILES; ++t) {
        const int p = pxbase + t*256 + tid;
        const int seg = tn[p];

        const unsigned mm = __match_any_sync(0xffffffffu, seg);
        if ((mm & lmask) == 0u) cnts[wid][seg] += __popc(mm);

        if (prev_seg >= 0) Atile[prev_seg*AROW + tid] = 0;
        Atile[seg*AROW + tid] = 0x3C00;   // f16 1.0
        prev_seg = seg;

        float v[EE];
#pragma unroll
        for (int e = 0; e < EE; ++e) v[e] = xn[e*PP + p];
        unsigned pk[8];
#pragma unroll
        for (int j = 0; j < 8; ++j)
            pk[j] = pack_f16x2(v[2*j], v[2*j+1]);
        uint4* xr = reinterpret_cast<uint4*>(&Xtile[tid*XROW]);
        xr[0] = make_uint4(pk[0], pk[1], pk[2], pk[3]);
        xr[1] = make_uint4(pk[4], pk[5], pk[6], pk[7]);
        __syncthreads();

#pragma unroll
        for (int j = 0; j < 8; ++j) {
            const int Ks = kh*8 + j;
            unsigned a0, a1, a2, a3, b0, b1;
            const unsigned aaddr = smemA
                + (unsigned)(((Mt*16 + (lane & 15))*AROW + Ks*16)*2 + (lane >> 4)*16);
            asm volatile("ldmatrix.sync.aligned.m8n8.x4.shared.b16 "
                         "{%0,%1,%2,%3},[%4];"
                         : "=r"(a0), "=r"(a1), "=r"(a2), "=r"(a3) : "r"(aaddr));
            const unsigned baddr = smemX
                + (unsigned)(((Ks*16 + (lane & 15))*XROW)*2 + Nt*16);
            asm volatile("ldmatrix.sync.aligned.m8n8.x2.trans.shared.b16 "
                         "{%0,%1},[%2];"
                         : "=r"(b0), "=r"(b1) : "r"(baddr));
            asm volatile("mma.sync.aligned.m16n8k16.row.col.f32.f16.f16.f32 "
                         "{%0,%1,%2,%3},{%4,%5,%6,%7},{%8,%9},{%0,%1,%2,%3};"
                         : "+f"(d0), "+f"(d1), "+f"(d2), "+f"(d3)
                         : "r"(a0), "r"(a1), "r"(a2), "r"(a3), "r"(b0), "r"(b1));
        }
        __syncthreads();
    }

    {
        const int r0 = Mt*16 + (lane >> 2);
        const int c0 = Nt*8 + (lane & 3)*2;
        atomicAdd(&bins[r0][c0],     d0);
        atomicAdd(&bins[r0][c0+1],   d1);
        atomicAdd(&bins[r0+8][c0],   d2);
        atomicAdd(&bins[r0+8][c0+1], d3);
    }
    __syncthreads();

    for (int i = tid; i < CC*EE; i += 256)
        atomicAdd(&g_sums[n*CC*EE + i], bins[i >> 4][i & 15]);
    if (tid < CC) {
        int s = 0;
#pragma unroll
        for (int w = 0; w < 8; ++w) s += cnts[w][tid];
        atomicAdd(&g_cnt[n*CC + tid], (float)s);
    }
}

// ---------------------------------------------------------------------------
// K2 (fused): var (R12-exact loop) / triplet / last-block finalize.
// Var blocks consume slices in REVERSE launch order so the earliest var
// waves re-read what pass 1 loaded LAST -> L2 hits instead of DRAM.
// ---------------------------------------------------------------------------
__device__ __forceinline__ void var_block(const float* __restrict__ x,
                                          const int* __restrict__ tgt,
                                          int n, int bx) {
    __shared__ float ms[CC][17];
    __shared__ float vb[8][CC];
    const int tid  = threadIdx.x;
    const int wid  = tid >> 5;
    const int lane = tid & 31;

    for (int i = tid; i < CC*EE; i += 256)
        ms[i/EE][i%EE] = g_sums[n*CC*EE + i] / g_cnt[n*CC + i/EE];
    for (int i = tid; i < 8*CC; i += 256) (&vb[0][0])[i] = 0.f;
    __syncthreads();

    const float* xn = x   + (size_t)n * EE * PP;
    const int*   tn = tgt + (size_t)n * PP;
    const unsigned lmask = (1u << lane) - 1u;

    int pbase = bx * PXB + tid;
    for (int it = 0; it < PXB/256; ++it, pbase += 256) {
        const int p = pbase;
        const int seg = tn[p];
        float d2 = 0.f;
#pragma unroll
        for (int e = 0; e < EE; ++e) {
            float diff = xn[e*PP + p] - ms[seg][e];
            d2 += diff * diff;
        }
        float h = sqrtf(d2) - 0.5f;
        h = fmaxf(h, 0.f);
        h = h * h;

        const unsigned mm = __match_any_sync(0xffffffffu, seg);
        const int rank = __popc(mm & lmask);
        const int gsz  = __popc(mm);
        const int gmax = __reduce_max_sync(0xffffffffu, gsz);
        for (int st = 1; st < gmax; st <<= 1) {
            const unsigned src = __fns(mm, 0, rank + st + 1);
            const bool valid = (src != 0xffffffffu);
            const int sl = valid ? (int)src : lane;
            const float oh = __shfl_sync(0xffffffffu, h, sl);
            if (valid) h += oh;
        }
        if (rank == 0) vb[wid][seg] += h;
    }
    __syncthreads();

    for (int i = tid; i < CC; i += 256) {
        float s = 0.f;
#pragma unroll
        for (int w = 0; w < 8; ++w) s += vb[w][i];
        atomicAdd(&g_var[n*CC + i], s);
    }
}

__device__ __forceinline__ void triplet_block(const int* __restrict__ ea,
                                              const int* __restrict__ er,
                                              int n, int rb) {
    __shared__ float cm[CC][EE];
    __shared__ float dr[200];
    __shared__ int r0s[200], r1s[200];
    __shared__ float da8[8];
    __shared__ int a0s[8], a1s[8];
    __shared__ float reds[256];
    __shared__ int   redc[256];
    const int tid = threadIdx.x;

    for (int i = tid; i < CC*EE; i += 256)
        cm[i/EE][i%EE] = g_sums[n*CC*EE + i] / g_cnt[n*CC + i/EE];
    __syncthreads();

    if (tid < 200) {
        int i0 = er[n*400 + tid], i1 = er[n*400 + 200 + tid];
        r0s[tid] = i0; r1s[tid] = i1;
        float s = 0.f;
#pragma unroll
        for (int e = 0; e < EE; ++e) {
            float df = cm[i0][e] - cm[i1][e] + 1e-6f;
            s += df * df;
        }
        dr[tid] = s;
    }
    if (tid < 8) {
        int a = rb*8 + tid;
        int i0 = ea[n*400 + a], i1 = ea[n*400 + 200 + a];
        a0s[tid] = i0; a1s[tid] = i1;
        float s = 0.f;
#pragma unroll
        for (int e = 0; e < EE; ++e) {
            float df = cm[i0][e] - cm[i1][e] + 1e-6f;
            s += df * df;
        }
        da8[tid] = s;
    }
    __syncthreads();

    float sum = 0.f; int cnt = 0;
    if (tid < 200) {
        const int rr0 = r0s[tid], rr1 = r1s[tid];
        const float drv = dr[tid];
#pragma unroll
        for (int a = 0; a < 8; ++a) {
            const int m = (a0s[a] == rr0) + (a0s[a] == rr1) +
                          (a1s[a] == rr0) + (a1s[a] == rr1);
            if (m == 1) {
                float t = 0.5f * (da8[a] - drv) + 0.01f;
                if (t > 0.f) { sum += t; cnt++; }
            }
        }
    }
    reds[tid] = sum; redc[tid] = cnt;
    __syncthreads();
    for (int s = 128; s > 0; s >>= 1) {
        if (tid < s) { reds[tid] += reds[tid + s]; redc[tid] += redc[tid + s]; }
        __syncthreads();
    }
    if (tid == 0) {
        atomicAdd(&g_tsum[n], reds[0]);
        atomicAdd(&g_tcnt[n], (float)redc[0]);
    }
}

__global__ __launch_bounds__(256) void k_var_trip(const float* __restrict__ x,
                                                  const int* __restrict__ tgt,
                                                  const int* __restrict__ ea,
                                                  const int* __restrict__ er,
                                                  float* __restrict__ out) {
    if (blockIdx.x < B1) {
        // reverse mapping: earliest-launched var blocks take the slices
        // pass 1 touched LAST (hot in L2)
        const int n  = NB - 1 - blockIdx.y;
        const int bx = B1 - 1 - blockIdx.x;
        var_block(x, tgt, n, bx);
    } else {
        triplet_block(ea, er, blockIdx.y, blockIdx.x - B1);
    }

    // ---- last-block finalize + state reset ----
    __threadfence();
    __shared__ unsigned isLast;
    const int tid = threadIdx.x;
    if (tid == 0)
        isLast = (atomicAdd(&g_ticket, 1u) == (unsigned)(VT_BLOCKS - 1));
    __syncthreads();
    if (!isLast) return;
    __threadfence();   // acquire: see all other blocks' atomics

    __shared__ float red[256];
    float acc = 0.f;
    if (tid < NB*CC) {
        float inv = 1.f / g_cnt[tid];
        float vt = g_var[tid] * inv;
        float s2 = 0.f;
#pragma unroll
        for (int e = 0; e < EE; ++e) {
            float m = g_sums[tid*EE + e] * inv;
            s2 += m * m;
        }
        float rg = sqrtf(s2) - 1.f;
        acc = (vt + rg * rg) * (1.f / (float)CC);
    }
    if (tid < NB) acc += (g_tcnt[tid] > 0.f) ? g_tsum[tid] / g_tcnt[tid] : 0.f;
    red[tid] = acc;
    __syncthreads();
    for (int s = 128; s > 0; s >>= 1) {
        if (tid < s) red[tid] += red[tid + s];
        __syncthreads();
    }
    if (tid == 0) out[0] = red[0] / 16.f;

    // re-zero all accumulator state for the next call (graph replay)
    for (int i = tid; i < NB*CC*EE; i += 256) g_sums[i] = 0.f;
    if (tid < NB*CC) { g_cnt[tid] = 0.f; g_var[tid] = 0.f; }
    if (tid < NB) { g_tsum[tid] = 0.f; g_tcnt[tid] = 0.f; }
    if (tid == 0) g_ticket = 0u;
}

// ---------------------------------------------------------------------------
extern "C" void kernel_launch(void* const* d_in, const int* in_sizes, int n_in,
                              void* d_out, int out_size) {
    const float* x   = (const float*)d_in[0];
    const int*   tgt = (const int*)d_in[1];
    const int*   ea  = (const int*)d_in[2];
    const int*   er  = (const int*)d_in[3];
    float* out = (float*)d_out;

    dim3 g(B1, NB);
    k_sums<<<g, 256>>>(x, tgt);
    dim3 gv(B1 + 25, NB);
    k_var_trip<<<gv, 256>>>(x, tgt, ea, er, out);
}

// round 16
// speedup vs baseline: 1.1986x; 1.0851x over previous
#include <cuda_runtime.h>
#include <cuda_fp16.h>
#include <cuda_bf16.h>
#include <cstdint>

#define NB 4
#define CC 24
#define EE 16
#define PP (768*768)
#define B1 288
#define PXB (PP/B1)        /* 2048 pixels per block */
#define TILES (PXB/256)    /* 8 tiles of 256 px */
#define AROW 264           /* one-hot row stride in shorts (528 B) */
#define XROW 24            /* x-tile row stride in shorts (48 B) */
#define VT_BLOCKS ((B1 + 25) * NB)   /* total blocks of k_var_trip */

__device__ float g_sums[NB*CC*EE];
__device__ float g_cnt[NB*CC];
__device__ float g_var[NB*CC];
__device__ float g_tsum[NB];
__device__ float g_tcnt[NB];
__device__ unsigned g_ticket;

// pack two f32 into f16x2: low half = a, high half = b
__device__ __forceinline__ unsigned pack_f16x2(float a, float b) {
    unsigned r;
    asm("cvt.rn.f16x2.f32 %0, %1, %2;" : "=r"(r) : "f"(b), "f"(a));
    return r;
}

// ---------------------------------------------------------------------------
// K1: segment sums via tensor cores. Counts via per-warp shared ATOMS.
// ---------------------------------------------------------------------------
__global__ __launch_bounds__(256) void k_sums(const float* __restrict__ x,
                                              const int* __restrict__ tgt) {
    const int n = blockIdx.y;
    __shared__ __align__(16) unsigned short Atile[32*AROW];   // one-hot [seg][px]
    __shared__ __align__(16) unsigned short Xtile[256*XROW];  // f16 [px][ch]
    __shared__ float bins[32][16];
    __shared__ int   cnts[8][CC];
    const int tid  = threadIdx.x;
    const int wid  = tid >> 5;
    const int lane = tid & 31;

    for (int i = tid; i < 32*AROW; i += 256) Atile[i] = 0;
    for (int i = tid; i < 512;     i += 256) (&bins[0][0])[i] = 0.f;
    for (int i = tid; i < 8*CC;    i += 256) (&cnts[0][0])[i] = 0;
    __syncthreads();

    const float* xn = x   + (size_t)n * EE * PP;
    const int*   tn = tgt + (size_t)n * PP;

    const int q  = wid >> 1;          // quadrant 0..3
    const int kh = wid & 1;           // K-half
    const int Mt = q >> 1, Nt = q & 1;
    const unsigned smemA = (unsigned)__cvta_generic_to_shared(Atile);
    const unsigned smemX = (unsigned)__cvta_generic_to_shared(Xtile);

    float d0 = 0.f, d1 = 0.f, d2 = 0.f, d3 = 0.f;
    int prev_seg = -1;
    const int pxbase = blockIdx.x * PXB;

    for (int t = 0; t < TILES; ++t) {
        const int p = pxbase + t*256 + tid;
        const int seg = tn[p];

        // counts: one shared atomic per pixel (per-warp row, ~2-3-way conflicts)
        atomicAdd(&cnts[wid][seg], 1);

        // unscatter previous one-hot, scatter new (2-byte writes)
        if (prev_seg >= 0) Atile[prev_seg*AROW + tid] = 0;
        Atile[seg*AROW + tid] = 0x3C00;   // f16 1.0
        prev_seg = seg;

        float v[EE];
#pragma unroll
        for (int e = 0; e < EE; ++e) v[e] = xn[e*PP + p];
        unsigned pk[8];
#pragma unroll
        for (int j = 0; j < 8; ++j)
            pk[j] = pack_f16x2(v[2*j], v[2*j+1]);
        uint4* xr = reinterpret_cast<uint4*>(&Xtile[tid*XROW]);
        xr[0] = make_uint4(pk[0], pk[1], pk[2], pk[3]);
        xr[1] = make_uint4(pk[4], pk[5], pk[6], pk[7]);
        __syncthreads();

#pragma unroll
        for (int j = 0; j < 8; ++j) {
            const int Ks = kh*8 + j;
            unsigned a0, a1, a2, a3, b0, b1;
            const unsigned aaddr = smemA
                + (unsigned)(((Mt*16 + (lane & 15))*AROW + Ks*16)*2 + (lane >> 4)*16);
            asm volatile("ldmatrix.sync.aligned.m8n8.x4.shared.b16 "
                         "{%0,%1,%2,%3},[%4];"
                         : "=r"(a0), "=r"(a1), "=r"(a2), "=r"(a3) : "r"(aaddr));
            const unsigned baddr = smemX
                + (unsigned)(((Ks*16 + (lane & 15))*XROW)*2 + Nt*16);
            asm volatile("ldmatrix.sync.aligned.m8n8.x2.trans.shared.b16 "
                         "{%0,%1},[%2];"
                         : "=r"(b0), "=r"(b1) : "r"(baddr));
            asm volatile("mma.sync.aligned.m16n8k16.row.col.f32.f16.f16.f32 "
                         "{%0,%1,%2,%3},{%4,%5,%6,%7},{%8,%9},{%0,%1,%2,%3};"
                         : "+f"(d0), "+f"(d1), "+f"(d2), "+f"(d3)
                         : "r"(a0), "r"(a1), "r"(a2), "r"(a3), "r"(b0), "r"(b1));
        }
        __syncthreads();
    }

    {
        const int r0 = Mt*16 + (lane >> 2);
        const int c0 = Nt*8 + (lane & 3)*2;
        atomicAdd(&bins[r0][c0],     d0);
        atomicAdd(&bins[r0][c0+1],   d1);
        atomicAdd(&bins[r0+8][c0],   d2);
        atomicAdd(&bins[r0+8][c0+1], d3);
    }
    __syncthreads();

    for (int i = tid; i < CC*EE; i += 256)
        atomicAdd(&g_sums[n*CC*EE + i], bins[i >> 4][i & 15]);
    if (tid < CC) {
        int s = 0;
#pragma unroll
        for (int w = 0; w < 8; ++w) s += cnts[w][tid];
        atomicAdd(&g_cnt[n*CC + tid], (float)s);
    }
}

// ---------------------------------------------------------------------------
// K2 (fused): var / triplet / last-block finalize.
// Var scatter: ONE shared atomic per pixel into per-warp bins (replaces the
// whole match/fns/shfl tree -> ~18 fewer instructions per pixel).
// ---------------------------------------------------------------------------
__device__ __forceinline__ void var_block(const float* __restrict__ x,
                                          const int* __restrict__ tgt,
                                          int n, int bx) {
    __shared__ float ms[CC][17];
    __shared__ float vb[8][CC];
    const int tid  = threadIdx.x;
    const int wid  = tid >> 5;

    for (int i = tid; i < CC*EE; i += 256)
        ms[i/EE][i%EE] = g_sums[n*CC*EE + i] / g_cnt[n*CC + i/EE];
    for (int i = tid; i < 8*CC; i += 256) (&vb[0][0])[i] = 0.f;
    __syncthreads();

    const float* xn = x   + (size_t)n * EE * PP;
    const int*   tn = tgt + (size_t)n * PP;

    int pbase = bx * PXB + tid;
    for (int it = 0; it < PXB/256; ++it, pbase += 256) {
        const int p = pbase;
        const int seg = tn[p];
        float d2 = 0.f;
#pragma unroll
        for (int e = 0; e < EE; ++e) {
            float diff = xn[e*PP + p] - ms[seg][e];
            d2 += diff * diff;
        }
        float h = sqrtf(d2) - 0.5f;
        h = fmaxf(h, 0.f);
        atomicAdd(&vb[wid][seg], h * h);
    }
    __syncthreads();

    for (int i = tid; i < CC; i += 256) {
        float s = 0.f;
#pragma unroll
        for (int w = 0; w < 8; ++w) s += vb[w][i];
        atomicAdd(&g_var[n*CC + i], s);
    }
}

__device__ __forceinline__ void triplet_block(const int* __restrict__ ea,
                                              const int* __restrict__ er,
                                              int n, int rb) {
    __shared__ float cm[CC][EE];
    __shared__ float dr[200];
    __shared__ int r0s[200], r1s[200];
    __shared__ float da8[8];
    __shared__ int a0s[8], a1s[8];
    __shared__ float reds[256];
    __shared__ int   redc[256];
    const int tid = threadIdx.x;

    for (int i = tid; i < CC*EE; i += 256)
        cm[i/EE][i%EE] = g_sums[n*CC*EE + i] / g_cnt[n*CC + i/EE];
    __syncthreads();

    if (tid < 200) {
        int i0 = er[n*400 + tid], i1 = er[n*400 + 200 + tid];
        r0s[tid] = i0; r1s[tid] = i1;
        float s = 0.f;
#pragma unroll
        for (int e = 0; e < EE; ++e) {
            float df = cm[i0][e] - cm[i1][e] + 1e-6f;
            s += df * df;
        }
        dr[tid] = s;
    }
    if (tid < 8) {
        int a = rb*8 + tid;
        int i0 = ea[n*400 + a], i1 = ea[n*400 + 200 + a];
        a0s[tid] = i0; a1s[tid] = i1;
        float s = 0.f;
#pragma unroll
        for (int e = 0; e < EE; ++e) {
            float df = cm[i0][e] - cm[i1][e] + 1e-6f;
            s += df * df;
        }
        da8[tid] = s;
    }
    __syncthreads();

    float sum = 0.f; int cnt = 0;
    if (tid < 200) {
        const int rr0 = r0s[tid], rr1 = r1s[tid];
        const float drv = dr[tid];
#pragma unroll
        for (int a = 0; a < 8; ++a) {
            const int m = (a0s[a] == rr0) + (a0s[a] == rr1) +
                          (a1s[a] == rr0) + (a1s[a] == rr1);
            if (m == 1) {
                float t = 0.5f * (da8[a] - drv) + 0.01f;
                if (t > 0.f) { sum += t; cnt++; }
            }
        }
    }
    reds[tid] = sum; redc[tid] = cnt;
    __syncthreads();
    for (int s = 128; s > 0; s >>= 1) {
        if (tid < s) { reds[tid] += reds[tid + s]; redc[tid] += redc[tid + s]; }
        __syncthreads();
    }
    if (tid == 0) {
        atomicAdd(&g_tsum[n], reds[0]);
        atomicAdd(&g_tcnt[n], (float)redc[0]);
    }
}

__global__ __launch_bounds__(256) void k_var_trip(const float* __restrict__ x,
                                                  const int* __restrict__ tgt,
                                                  const int* __restrict__ ea,
                                                  const int* __restrict__ er,
                                                  float* __restrict__ out) {
    if (blockIdx.x < B1) {
        // reverse mapping: earliest var blocks take slices pass 1 touched last
        const int n  = NB - 1 - blockIdx.y;
        const int bx = B1 - 1 - blockIdx.x;
        var_block(x, tgt, n, bx);
    } else {
        triplet_block(ea, er, blockIdx.y, blockIdx.x - B1);
    }

    // ---- last-block finalize + state reset ----
    __threadfence();
    __shared__ unsigned isLast;
    const int tid = threadIdx.x;
    if (tid == 0)
        isLast = (atomicAdd(&g_ticket, 1u) == (unsigned)(VT_BLOCKS - 1));
    __syncthreads();
    if (!isLast) return;
    __threadfence();   // acquire: see all other blocks' atomics

    __shared__ float red[256];
    float acc = 0.f;
    if (tid < NB*CC) {
        float inv = 1.f / g_cnt[tid];
        float vt = g_var[tid] * inv;
        float s2 = 0.f;
#pragma unroll
        for (int e = 0; e < EE; ++e) {
            float m = g_sums[tid*EE + e] * inv;
            s2 += m * m;
        }
        float rg = sqrtf(s2) - 1.f;
        acc = (vt + rg * rg) * (1.f / (float)CC);
    }
    if (tid < NB) acc += (g_tcnt[tid] > 0.f) ? g_tsum[tid] / g_tcnt[tid] : 0.f;
    red[tid] = acc;
    __syncthreads();
    for (int s = 128; s > 0; s >>= 1) {
        if (tid < s) red[tid] += red[tid + s];
        __syncthreads();
    }
    if (tid == 0) out[0] = red[0] / 16.f;

    // re-zero all accumulator state for the next call (graph replay)
    for (int i = tid; i < NB*CC*EE; i += 256) g_sums[i] = 0.f;
    if (tid < NB*CC) { g_cnt[tid] = 0.f; g_var[tid] = 0.f; }
    if (tid < NB) { g_tsum[tid] = 0.f; g_tcnt[tid] = 0.f; }
    if (tid == 0) g_ticket = 0u;
}

// ---------------------------------------------------------------------------
extern "C" void kernel_launch(void* const* d_in, const int* in_sizes, int n_in,
                              void* d_out, int out_size) {
    const float* x   = (const float*)d_in[0];
    const int*   tgt = (const int*)d_in[1];
    const int*   ea  = (const int*)d_in[2];
    const int*   er  = (const int*)d_in[3];
    float* out = (float*)d_out;

    dim3 g(B1, NB);
    k_sums<<<g, 256>>>(x, tgt);
    dim3 gv(B1 + 25, NB);
    k_var_trip<<<gv, 256>>>(x, tgt, ea, er, out);
}